// round 10
// baseline (speedup 1.0000x reference)
#include <cuda_runtime.h>
#include <math.h>

#define N 512
#define D 128
#define DEPTH 4
#define TT 32
#define SC 16            // real s-chunk size
#define WC 32            // W-chunk size
#define NREAL 272        // sum over a=0..15 of (2a+2)
#define NBLK 336         // 272 real + 64 W blocks
#define NSLICE 36        // 32 real + 4 W slices
#define STR 132
#define PSTR 20
#define CSTR 20

// ---------------- scratch ----------------
__device__ float g_q[N*D];
__device__ float g_X[N*D];
__device__ float g_lr[N], g_am[N], g_dk[N];
__device__ float g_A[DEPTH*N*D];
__device__ float g_G[DEPTH*N*D];
__device__ float g_WT[DEPTH*D*D];
__device__ float g_Chat[N*N];
__device__ float g_Yp[NSLICE*N*D];
__device__ unsigned int g_arrive;

__device__ __forceinline__ float siluf(float z){
    float s = 1.f/(1.f+__expf(-z));
    return z*s;
}
__device__ __forceinline__ float dsiluf(float z){
    float s = 1.f/(1.f+__expf(-z));
    return s*(1.f + z*(1.f-s));
}

// ---------------- transpose W_mem (+ reset grid barrier counter) ----------------
__global__ void tr_kernel(const float* __restrict__ Wmem){
    if (blockIdx.x == 0 && threadIdx.x == 0) g_arrive = 0u;
    int l = blockIdx.x;
    for (int e = threadIdx.x; e < D*D; e += blockDim.x){
        int j = e >> 7, i = e & 127;
        g_WT[l*D*D + e] = Wmem[l*D*D + i*D + j];
    }
}

// ---------------- half-GEMV: 4 tokens, 64 i's, unroll 32 ----------------
__device__ __forceinline__ void gemv4h(const float sxa[4][D], const float* __restrict__ Wp,
                                       int j, int h, float z[4]){
    const float* W = Wp + (h*64)*D + j;
    z[0]=0.f; z[1]=0.f; z[2]=0.f; z[3]=0.f;
    const int base = h*64;
    #pragma unroll
    for (int i = 0; i < 64; i += 32){
        float w[32];
        #pragma unroll
        for (int u = 0; u < 32; u++) w[u] = W[(i+u)*D];
        #pragma unroll
        for (int m = 0; m < 4; m++){
            const float* xr = &sxa[m][base+i];
            float acc = 0.f;
            #pragma unroll
            for (int q = 0; q < 32; q += 4){
                float4 x = *reinterpret_cast<const float4*>(&xr[q]);
                acc += x.x*w[q] + x.y*w[q+1] + x.z*w[q+2] + x.w*w[q+3];
            }
            z[m] += acc;
        }
    }
}

// ---------------- per-token MLP fwd+bwd: 4 tokens/block, 256 thr ----------------
__global__ __launch_bounds__(256) void token_kernel(const float* __restrict__ seq,
                             const float* __restrict__ Wmem,
                             const float* __restrict__ Wq,
                             const float* __restrict__ Wkv,
                             const float* __restrict__ Wmom,
                             const float* __restrict__ Wstep,
                             const float* __restrict__ Wdecay){
    int t0 = blockIdx.x*4;
    int tid = threadIdx.x;
    int j = tid & 127;
    int h = tid >> 7;
    __shared__ float sx[4][D];
    __shared__ float sA[4][D];
    __shared__ float sB[4][D];
    __shared__ float sv[4][D];
    __shared__ float szp[3][2][4][D];
    __shared__ float red[12][4];

    for (int e = tid; e < 4*D; e += 256){
        int m = e >> 7, jj = e & 127;
        sx[m][jj] = seq[(t0+m)*D + jj];
    }
    __syncthreads();

    if (h == 0){
        float ws = Wstep[j], wm = Wmom[j], wd = Wdecay[j];
        #pragma unroll
        for (int m = 0; m < 4; m++){
            float xv = sx[m][j];
            float p0 = xv*ws, p1 = xv*wm, p2 = xv*wd;
            #pragma unroll
            for (int o = 16; o > 0; o >>= 1){
                p0 += __shfl_xor_sync(0xffffffffu, p0, o);
                p1 += __shfl_xor_sync(0xffffffffu, p1, o);
                p2 += __shfl_xor_sync(0xffffffffu, p2, o);
            }
            if ((j & 31) == 0){ red[m*3+0][j>>5]=p0; red[m*3+1][j>>5]=p1; red[m*3+2][j>>5]=p2; }
        }
    }

    // q,k,v partials
    {
        float qa[4]={0,0,0,0}, ka[4]={0,0,0,0}, va[4]={0,0,0,0};
        const float* Wqh  = Wq  + (h*64)*D + j;
        const float* Wkh  = Wkv + (h*64)*2*D + j;
        const float* Wvh  = Wkv + (h*64)*2*D + D + j;
        const int base = h*64;
        for (int i = 0; i < 64; i += 8){
            float wq[8], wk[8], wv[8];
            #pragma unroll
            for (int u = 0; u < 8; u++){
                wq[u] = Wqh[(i+u)*D];
                wk[u] = Wkh[(i+u)*2*D];
                wv[u] = Wvh[(i+u)*2*D];
            }
            #pragma unroll
            for (int m = 0; m < 4; m++){
                const float* xr = &sx[m][base+i];
                float4 xa = *reinterpret_cast<const float4*>(&xr[0]);
                float4 xb = *reinterpret_cast<const float4*>(&xr[4]);
                qa[m] += xa.x*wq[0]+xa.y*wq[1]+xa.z*wq[2]+xa.w*wq[3]
                       + xb.x*wq[4]+xb.y*wq[5]+xb.z*wq[6]+xb.w*wq[7];
                ka[m] += xa.x*wk[0]+xa.y*wk[1]+xa.z*wk[2]+xa.w*wk[3]
                       + xb.x*wk[4]+xb.y*wk[5]+xb.z*wk[6]+xb.w*wk[7];
                va[m] += xa.x*wv[0]+xa.y*wv[1]+xa.z*wv[2]+xa.w*wv[3]
                       + xb.x*wv[4]+xb.y*wv[5]+xb.z*wv[6]+xb.w*wv[7];
            }
        }
        #pragma unroll
        for (int m = 0; m < 4; m++){
            szp[0][h][m][j] = qa[m];
            szp[1][h][m][j] = ka[m];
            szp[2][h][m][j] = va[m];
        }
    }
    __syncthreads();
    if (h == 0){
        if (j < 4){
            g_lr[t0+j] = red[j*3+0][0]+red[j*3+0][1]+red[j*3+0][2]+red[j*3+0][3];
            g_am[t0+j] = red[j*3+1][0]+red[j*3+1][1]+red[j*3+1][2]+red[j*3+1][3];
            float dz = red[j*3+2][0]+red[j*3+2][1]+red[j*3+2][2]+red[j*3+2][3];
            g_dk[t0+j] = 1.f - 1.f/(1.f+__expf(-dz));
        }
        #pragma unroll
        for (int m = 0; m < 4; m++){
            g_q[(t0+m)*D + j] = szp[0][0][m][j] + szp[0][1][m][j];
            float kk = szp[1][0][m][j] + szp[1][1][m][j];
            sA[m][j] = kk; g_A[0*N*D + (t0+m)*D + j] = kk;
            sv[m][j] = szp[2][0][m][j] + szp[2][1][m][j];
        }
    }
    __syncthreads();

    float z1[4], z2[4], z3[4], zp[4], z[4];

    gemv4h(sA, Wmem + 0*D*D, j, h, zp);
    #pragma unroll
    for (int m = 0; m < 4; m++) szp[0][h][m][j] = zp[m];
    __syncthreads();
    #pragma unroll
    for (int m = 0; m < 4; m++){
        z[m] = szp[0][0][m][j] + szp[0][1][m][j]; z1[m] = z[m];
        if (h == 0){ float x1 = siluf(z[m]); sB[m][j] = x1; g_A[1*N*D + (t0+m)*D + j] = x1; }
    }
    __syncthreads();

    gemv4h(sB, Wmem + 1*D*D, j, h, zp);
    #pragma unroll
    for (int m = 0; m < 4; m++) szp[0][h][m][j] = zp[m];
    __syncthreads();
    #pragma unroll
    for (int m = 0; m < 4; m++){
        z[m] = szp[0][0][m][j] + szp[0][1][m][j]; z2[m] = z[m];
        if (h == 0){ float x2 = siluf(z[m]); sA[m][j] = x2; g_A[2*N*D + (t0+m)*D + j] = x2; }
    }
    __syncthreads();

    gemv4h(sA, Wmem + 2*D*D, j, h, zp);
    #pragma unroll
    for (int m = 0; m < 4; m++) szp[0][h][m][j] = zp[m];
    __syncthreads();
    #pragma unroll
    for (int m = 0; m < 4; m++){
        z[m] = szp[0][0][m][j] + szp[0][1][m][j]; z3[m] = z[m];
        if (h == 0){ float x3 = siluf(z[m]); sB[m][j] = x3; g_A[3*N*D + (t0+m)*D + j] = x3; }
    }
    __syncthreads();

    gemv4h(sB, Wmem + 3*D*D, j, h, zp);
    #pragma unroll
    for (int m = 0; m < 4; m++) szp[0][h][m][j] = zp[m];
    __syncthreads();
    #pragma unroll
    for (int m = 0; m < 4; m++){
        z[m] = szp[0][0][m][j] + szp[0][1][m][j];
        if (h == 0){
            float gg = (z[m] - sv[m][j]) * (2.f/(float)D);
            sA[m][j] = gg; g_G[3*N*D + (t0+m)*D + j] = gg;
        }
    }
    __syncthreads();

    gemv4h(sA, g_WT + 3*D*D, j, h, zp);
    #pragma unroll
    for (int m = 0; m < 4; m++) szp[0][h][m][j] = zp[m];
    __syncthreads();
    #pragma unroll
    for (int m = 0; m < 4; m++){
        z[m] = szp[0][0][m][j] + szp[0][1][m][j];
        if (h == 0){
            float gg = z[m]*dsiluf(z3[m]);
            sB[m][j] = gg; g_G[2*N*D + (t0+m)*D + j] = gg;
        }
    }
    __syncthreads();

    gemv4h(sB, g_WT + 2*D*D, j, h, zp);
    #pragma unroll
    for (int m = 0; m < 4; m++) szp[0][h][m][j] = zp[m];
    __syncthreads();
    #pragma unroll
    for (int m = 0; m < 4; m++){
        z[m] = szp[0][0][m][j] + szp[0][1][m][j];
        if (h == 0){
            float gg = z[m]*dsiluf(z2[m]);
            sA[m][j] = gg; g_G[1*N*D + (t0+m)*D + j] = gg;
        }
    }
    __syncthreads();

    gemv4h(sA, g_WT + 1*D*D, j, h, zp);
    #pragma unroll
    for (int m = 0; m < 4; m++) szp[0][h][m][j] = zp[m];
    __syncthreads();
    if (h == 0){
        #pragma unroll
        for (int m = 0; m < 4; m++){
            float zz = szp[0][0][m][j] + szp[0][1][m][j];
            g_G[0*N*D + (t0+m)*D + j] = zz*dsiluf(z1[m]);
        }
    }
}

// ---------------- scan-coefficient matrix (parallel over s) ----------------
__global__ void chat_kernel(){
    __shared__ float sam[N], sdk[N];
    int s = blockIdx.x*128 + threadIdx.x;
    for (int i = threadIdx.x; i < N; i += 128){ sam[i] = g_am[i]; sdk[i] = g_dk[i]; }
    __syncthreads();
    float m = 0.f, c = 0.f;
    float nl = -g_lr[s];
    for (int t = 0; t < N; t++){
        float out;
        if (t < s) out = 0.f;
        else if (t == s){ m = 1.f; c = 1.f; out = nl; }
        else {
            m *= sam[t];
            c = sdk[t]*c + m;
            out = nl*c;
        }
        g_Chat[t*N + s] = out;
    }
}

// ---------------- grid barrier (all NBLK blocks co-resident by construction) ----------------
__device__ __forceinline__ void gridbar(unsigned int target){
    __syncthreads();
    if (threadIdx.x == 0){
        __threadfence();
        atomicAdd(&g_arrive, 1u);
        while (*((volatile unsigned int*)&g_arrive) < target) { }
        __threadfence();
    }
    __syncthreads();
}

// ---------------- persistent fused kernel: 4 x (layer + reduce) ----------------
__global__ __launch_bounds__(256, 4) void mega_kernel(const float* __restrict__ Wmem,
                                                      float* __restrict__ out){
    extern __shared__ float sm[];
    float* Xs = sm;                 // [TT][STR]
    float* As = Xs + TT*STR;        // [SC][STR]
    float* Gs = As + SC*STR;        // [WC][STR]
    float* Cs = Gs + WC*STR;        // [TT][CSTR]
    float* Ps = Cs + TT*CSTR;       // [TT][PSTR]

    int id = blockIdx.x;
    int a, b; bool isW;
    if (id < NREAL){
        int r = id; a = 0;
        while (r >= 2*a + 2){ r -= 2*a + 2; a++; }
        b = r; isW = false;
    } else {
        int q = id - NREAL; a = q >> 2; b = q & 3; isW = true;
    }
    int t0 = a*TT;
    int tid = threadIdx.x;
    unsigned int bar = 0;

    #pragma unroll 1
    for (int layer = 0; layer < DEPTH; layer++){
        // ================= layer phase =================
        // load X tile
        for (int e = tid; e < TT*32; e += 256){
            int t = e >> 5, k4 = (e & 31)*4;
            float4 v;
            if (layer == 0)
                v = *reinterpret_cast<const float4*>(&g_q[(t0+t)*D + k4]);
            else
                v = __ldcg(reinterpret_cast<const float4*>(&g_X[(t0+t)*D + k4]));
            *reinterpret_cast<float4*>(&Xs[t*STR + k4]) = v;
        }
        if (!isW){
            const float* Al = g_A + layer*N*D;
            const float* Gl = g_G + layer*N*D;
            int s0 = b*SC;
            for (int e = tid; e < SC*32; e += 256){
                int r = e >> 5, k4 = (e & 31)*4;
                *reinterpret_cast<float4*>(&As[r*STR + k4]) =
                    *reinterpret_cast<const float4*>(&Al[(s0+r)*D + k4]);
            }
            for (int e = tid; e < SC*32; e += 256){
                int r = e >> 5, k4 = (e & 31)*4;
                *reinterpret_cast<float4*>(&Gs[r*STR + k4]) =
                    *reinterpret_cast<const float4*>(&Gl[(s0+r)*D + k4]);
            }
            for (int e = tid; e < TT*4; e += 256){
                int t = e >> 2, s4 = (e & 3)*4;
                *reinterpret_cast<float4*>(&Cs[t*CSTR + s4]) =
                    *reinterpret_cast<const float4*>(&g_Chat[(t0+t)*N + s0 + s4]);
            }
        } else {
            const float* Wl = Wmem + layer*D*D;
            int w0 = b*WC;
            for (int e = tid; e < WC*32; e += 256){
                int r = e >> 5, k4 = (e & 31)*4;
                *reinterpret_cast<float4*>(&Gs[r*STR + k4]) =
                    *reinterpret_cast<const float4*>(&Wl[(w0+r)*D + k4]);
            }
        }
        __syncthreads();

        // phase 1 (real): S = (X @ A^T) ⊙ Chat -> Ps
        if (!isW){
            int sx16 = tid & 15;
            int tg   = tid >> 4;
            float c0 = 0.f, c1 = 0.f;
            const float* ar  = As + sx16*STR;
            const float* x0r = Xs + (tg*2+0)*STR;
            const float* x1r = Xs + (tg*2+1)*STR;
            #pragma unroll 8
            for (int k = 0; k < D; k += 4){
                float4 av = *reinterpret_cast<const float4*>(&ar[k]);
                float4 x0 = *reinterpret_cast<const float4*>(&x0r[k]);
                float4 x1 = *reinterpret_cast<const float4*>(&x1r[k]);
                c0 += x0.x*av.x + x0.y*av.y + x0.z*av.z + x0.w*av.w;
                c1 += x1.x*av.x + x1.y*av.y + x1.z*av.z + x1.w*av.w;
            }
            Ps[(tg*2+0)*PSTR + sx16] = c0 * Cs[(tg*2+0)*CSTR + sx16];
            Ps[(tg*2+1)*PSTR + sx16] = c1 * Cs[(tg*2+1)*CSTR + sx16];
        }
        __syncthreads();

        // phase 2: Y_slice = P @ G
        {
            int tx = tid & 31, ty = tid >> 5;
            const float* Psrc = isW ? (Xs + b*WC) : Ps;
            int pst = isW ? STR : PSTR;
            int sc  = isW ? WC : SC;

            float y[4][4];
            #pragma unroll
            for (int i = 0; i < 4; i++)
                #pragma unroll
                for (int jj = 0; jj < 4; jj++) y[i][jj] = 0.f;

            #pragma unroll 4
            for (int s = 0; s < sc; s += 4){
                float4 g0 = *reinterpret_cast<const float4*>(&Gs[(s+0)*STR + tx*4]);
                float4 g1 = *reinterpret_cast<const float4*>(&Gs[(s+1)*STR + tx*4]);
                float4 g2 = *reinterpret_cast<const float4*>(&Gs[(s+2)*STR + tx*4]);
                float4 g3 = *reinterpret_cast<const float4*>(&Gs[(s+3)*STR + tx*4]);
                #pragma unroll
                for (int i = 0; i < 4; i++){
                    float4 p = *reinterpret_cast<const float4*>(&Psrc[(ty*4+i)*pst + s]);
                    y[i][0] += p.x*g0.x + p.y*g1.x + p.z*g2.x + p.w*g3.x;
                    y[i][1] += p.x*g0.y + p.y*g1.y + p.z*g2.y + p.w*g3.y;
                    y[i][2] += p.x*g0.z + p.y*g1.z + p.z*g2.z + p.w*g3.z;
                    y[i][3] += p.x*g0.w + p.y*g1.w + p.z*g2.w + p.w*g3.w;
                }
            }
            int slice = isW ? (32 + b) : b;
            #pragma unroll
            for (int i = 0; i < 4; i++){
                float4 v; v.x=y[i][0]; v.y=y[i][1]; v.z=y[i][2]; v.w=y[i][3];
                *reinterpret_cast<float4*>(&g_Yp[((slice*N) + t0 + ty*4 + i)*D + tx*4]) = v;
            }
        }

        bar += NBLK;
        gridbar(bar);

        // ================= reduce phase =================
        if (id < 256){
            int t  = id*2 + (tid >> 7);
            int lt = tid & 127;
            int tx = lt & 31, sg = lt >> 5;
            const float4* Yp = reinterpret_cast<const float4*>(g_Yp);
            int idx = t*32 + tx;

            float4 acc = __ldcg(&Yp[(32 + sg)*(N*32) + idx]);
            int nr = (t >> 4) + 1;
            #pragma unroll 4
            for (int c = sg; c < nr; c += 4){
                float4 p = __ldcg(&Yp[c*(N*32) + idx]);
                acc.x += p.x; acc.y += p.y; acc.z += p.z; acc.w += p.w;
            }

            float4* sred = reinterpret_cast<float4*>(sm);
            sred[tid] = acc;
            __syncthreads();
            if (sg == 0){
                float4 aa = sred[(tid & 128) + tx +  0];
                float4 bb = sred[(tid & 128) + tx + 32];
                float4 cc = sred[(tid & 128) + tx + 64];
                float4 dd = sred[(tid & 128) + tx + 96];
                float ax = aa.x+bb.x+cc.x+dd.x;
                float ay = aa.y+bb.y+cc.y+dd.y;
                float az = aa.z+bb.z+cc.z+dd.z;
                float aw = aa.w+bb.w+cc.w+dd.w;
                float4 r;
                if (layer == DEPTH-1){ r.x = ax; r.y = ay; r.z = az; r.w = aw; }
                else { r.x = siluf(ax); r.y = siluf(ay); r.z = siluf(az); r.w = siluf(aw); }
                float4* dst = (layer == DEPTH-1) ? reinterpret_cast<float4*>(out)
                                                 : reinterpret_cast<float4*>(g_X);
                dst[idx] = r;
            }
        }

        if (layer < DEPTH-1){
            bar += NBLK;
            gridbar(bar);
        }
    }
}

// ---------------- launch ----------------
extern "C" void kernel_launch(void* const* d_in, const int* in_sizes, int n_in,
                              void* d_out, int out_size){
    const float* seq    = (const float*)d_in[0];
    const float* Wmem   = (const float*)d_in[1];
    const float* Wq     = (const float*)d_in[2];
    const float* Wkv    = (const float*)d_in[3];
    const float* Wmom   = (const float*)d_in[4];
    const float* Wstep  = (const float*)d_in[5];
    const float* Wdecay = (const float*)d_in[6];
    float* out = (float*)d_out;

    size_t smem = (size_t)(TT*STR + SC*STR + WC*STR + TT*CSTR + TT*PSTR)*sizeof(float); // 47360
    cudaFuncSetAttribute(mega_kernel, cudaFuncAttributeMaxDynamicSharedMemorySize, (int)smem);

    tr_kernel<<<DEPTH, 128>>>(Wmem);
    token_kernel<<<N/4, 256>>>(seq, Wmem, Wq, Wkv, Wmom, Wstep, Wdecay);
    chat_kernel<<<4, 128>>>();
    mega_kernel<<<NBLK, 256, smem>>>(Wmem, out);
}

// round 11
// speedup vs baseline: 1.0455x; 1.0455x over previous
#include <cuda_runtime.h>
#include <math.h>

#define N 512
#define D 128
#define DEPTH 4
#define TT 32
#define SC 16            // real s-chunk size
#define WC 32            // W-chunk size
#define NREAL 272        // sum over a=0..15 of (2a+2)
#define NBLK 336         // 272 real + 64 W blocks
#define NSLICE 36        // 32 real + 4 W slices
#define STR 132
#define PSTR 20
#define CSTR 20

// ---------------- scratch ----------------
__device__ float g_q[N*D];
__device__ float g_X[N*D];
__device__ float g_lr[N], g_am[N], g_dk[N];
__device__ float g_A[DEPTH*N*D];
__device__ float g_G[DEPTH*N*D];
__device__ float g_WT[DEPTH*D*D];
__device__ float g_Chat[N*N];
__device__ float g_Yp[NSLICE*N*D];

__device__ __forceinline__ float siluf(float z){
    float s = 1.f/(1.f+__expf(-z));
    return z*s;
}
__device__ __forceinline__ float dsiluf(float z){
    float s = 1.f/(1.f+__expf(-z));
    return s*(1.f + z*(1.f-s));
}

// ---------------- transpose W_mem ----------------
__global__ void tr_kernel(const float* __restrict__ Wmem){
    int l = blockIdx.x;
    for (int e = threadIdx.x; e < D*D; e += blockDim.x){
        int j = e >> 7, i = e & 127;
        g_WT[l*D*D + e] = Wmem[l*D*D + i*D + j];
    }
}

// ---------------- 64 column-strided weight loads into registers ----------------
__device__ __forceinline__ void ldw64(const float* __restrict__ p, float w[64]){
    #pragma unroll
    for (int u = 0; u < 64; u++) w[u] = p[u*D];
}

// ---------------- 4-token x 64-i FMA with preloaded weights ----------------
__device__ __forceinline__ void fmaw(const float sxa[4][D], const float w[64],
                                     int base, float z[4]){
    #pragma unroll
    for (int m = 0; m < 4; m++){
        const float* xr = &sxa[m][base];
        float a0 = 0.f, a1 = 0.f;
        #pragma unroll
        for (int q = 0; q < 64; q += 8){
            float4 xa = *reinterpret_cast<const float4*>(&xr[q]);
            float4 xb = *reinterpret_cast<const float4*>(&xr[q+4]);
            a0 += xa.x*w[q]   + xa.y*w[q+1] + xa.z*w[q+2] + xa.w*w[q+3];
            a1 += xb.x*w[q+4] + xb.y*w[q+5] + xb.z*w[q+6] + xb.w*w[q+7];
        }
        z[m] = a0 + a1;
    }
}

// ---------------- per-token MLP fwd+bwd with cross-stage weight prefetch ----------------
__global__ __launch_bounds__(256) void token_kernel(const float* __restrict__ seq,
                             const float* __restrict__ Wmem,
                             const float* __restrict__ Wq,
                             const float* __restrict__ Wkv,
                             const float* __restrict__ Wmom,
                             const float* __restrict__ Wstep,
                             const float* __restrict__ Wdecay){
    int t0 = blockIdx.x*4;
    int tid = threadIdx.x;
    int j = tid & 127;
    int h = tid >> 7;
    const int base = h*64;
    const int coff = base*D + j;          // column offset for this thread's weight stream

    __shared__ float sx[4][D];
    __shared__ float sA[4][D];
    __shared__ float sB[4][D];
    __shared__ float sv[4][D];
    __shared__ float szp[3][2][4][D];
    __shared__ float red[12][4];

    for (int e = tid; e < 4*D; e += 256){
        int m = e >> 7, jj = e & 127;
        sx[m][jj] = seq[(t0+m)*D + jj];
    }
    __syncthreads();

    if (h == 0){
        float ws = Wstep[j], wm = Wmom[j], wd = Wdecay[j];
        #pragma unroll
        for (int m = 0; m < 4; m++){
            float xv = sx[m][j];
            float p0 = xv*ws, p1 = xv*wm, p2 = xv*wd;
            #pragma unroll
            for (int o = 16; o > 0; o >>= 1){
                p0 += __shfl_xor_sync(0xffffffffu, p0, o);
                p1 += __shfl_xor_sync(0xffffffffu, p1, o);
                p2 += __shfl_xor_sync(0xffffffffu, p2, o);
            }
            if ((j & 31) == 0){ red[m*3+0][j>>5]=p0; red[m*3+1][j>>5]=p1; red[m*3+2][j>>5]=p2; }
        }
    }

    // prefetch stage-0 weights (W0) while q/k/v runs
    float wA[64], wB[64];
    ldw64(Wmem + coff, wA);

    // q,k,v partials
    {
        float qa[4]={0,0,0,0}, ka[4]={0,0,0,0}, va[4]={0,0,0,0};
        const float* Wqh  = Wq  + base*D + j;
        const float* Wkh  = Wkv + base*2*D + j;
        const float* Wvh  = Wkv + base*2*D + D + j;
        for (int i = 0; i < 64; i += 8){
            float wq[8], wk[8], wv[8];
            #pragma unroll
            for (int u = 0; u < 8; u++){
                wq[u] = Wqh[(i+u)*D];
                wk[u] = Wkh[(i+u)*2*D];
                wv[u] = Wvh[(i+u)*2*D];
            }
            #pragma unroll
            for (int m = 0; m < 4; m++){
                const float* xr = &sx[m][base+i];
                float4 xa = *reinterpret_cast<const float4*>(&xr[0]);
                float4 xb = *reinterpret_cast<const float4*>(&xr[4]);
                qa[m] += xa.x*wq[0]+xa.y*wq[1]+xa.z*wq[2]+xa.w*wq[3]
                       + xb.x*wq[4]+xb.y*wq[5]+xb.z*wq[6]+xb.w*wq[7];
                ka[m] += xa.x*wk[0]+xa.y*wk[1]+xa.z*wk[2]+xa.w*wk[3]
                       + xb.x*wk[4]+xb.y*wk[5]+xb.z*wk[6]+xb.w*wk[7];
                va[m] += xa.x*wv[0]+xa.y*wv[1]+xa.z*wv[2]+xa.w*wv[3]
                       + xb.x*wv[4]+xb.y*wv[5]+xb.z*wv[6]+xb.w*wv[7];
            }
        }
        #pragma unroll
        for (int m = 0; m < 4; m++){
            szp[0][h][m][j] = qa[m];
            szp[1][h][m][j] = ka[m];
            szp[2][h][m][j] = va[m];
        }
    }
    __syncthreads();
    if (h == 0){
        if (j < 4){
            g_lr[t0+j] = red[j*3+0][0]+red[j*3+0][1]+red[j*3+0][2]+red[j*3+0][3];
            g_am[t0+j] = red[j*3+1][0]+red[j*3+1][1]+red[j*3+1][2]+red[j*3+1][3];
            float dz = red[j*3+2][0]+red[j*3+2][1]+red[j*3+2][2]+red[j*3+2][3];
            g_dk[t0+j] = 1.f - 1.f/(1.f+__expf(-dz));
        }
        #pragma unroll
        for (int m = 0; m < 4; m++){
            g_q[(t0+m)*D + j] = szp[0][0][m][j] + szp[0][1][m][j];
            float kk = szp[1][0][m][j] + szp[1][1][m][j];
            sA[m][j] = kk; g_A[0*N*D + (t0+m)*D + j] = kk;
            sv[m][j] = szp[2][0][m][j] + szp[2][1][m][j];
        }
    }
    __syncthreads();

    float z1[4], z2[4], z3[4], zp[4], z[4];

    // stage 0: z1 = k @ W0  (weights in wA; prefetch W1 -> wB)
    ldw64(Wmem + 1*D*D + coff, wB);
    fmaw(sA, wA, base, zp);
    #pragma unroll
    for (int m = 0; m < 4; m++) szp[0][h][m][j] = zp[m];
    __syncthreads();
    #pragma unroll
    for (int m = 0; m < 4; m++){
        z[m] = szp[0][0][m][j] + szp[0][1][m][j]; z1[m] = z[m];
        if (h == 0){ float x1 = siluf(z[m]); sB[m][j] = x1; g_A[1*N*D + (t0+m)*D + j] = x1; }
    }
    __syncthreads();

    // stage 1: z2 = x1 @ W1  (wB; prefetch W2 -> wA)
    ldw64(Wmem + 2*D*D + coff, wA);
    fmaw(sB, wB, base, zp);
    #pragma unroll
    for (int m = 0; m < 4; m++) szp[0][h][m][j] = zp[m];
    __syncthreads();
    #pragma unroll
    for (int m = 0; m < 4; m++){
        z[m] = szp[0][0][m][j] + szp[0][1][m][j]; z2[m] = z[m];
        if (h == 0){ float x2 = siluf(z[m]); sA[m][j] = x2; g_A[2*N*D + (t0+m)*D + j] = x2; }
    }
    __syncthreads();

    // stage 2: z3 = x2 @ W2  (wA; prefetch W3 -> wB)
    ldw64(Wmem + 3*D*D + coff, wB);
    fmaw(sA, wA, base, zp);
    #pragma unroll
    for (int m = 0; m < 4; m++) szp[0][h][m][j] = zp[m];
    __syncthreads();
    #pragma unroll
    for (int m = 0; m < 4; m++){
        z[m] = szp[0][0][m][j] + szp[0][1][m][j]; z3[m] = z[m];
        if (h == 0){ float x3 = siluf(z[m]); sB[m][j] = x3; g_A[3*N*D + (t0+m)*D + j] = x3; }
    }
    __syncthreads();

    // stage 3: z4 = x3 @ W3 ; g3  (wB; prefetch WT3 -> wA)
    ldw64(g_WT + 3*D*D + coff, wA);
    fmaw(sB, wB, base, zp);
    #pragma unroll
    for (int m = 0; m < 4; m++) szp[0][h][m][j] = zp[m];
    __syncthreads();
    #pragma unroll
    for (int m = 0; m < 4; m++){
        z[m] = szp[0][0][m][j] + szp[0][1][m][j];
        if (h == 0){
            float gg = (z[m] - sv[m][j]) * (2.f/(float)D);
            sA[m][j] = gg; g_G[3*N*D + (t0+m)*D + j] = gg;
        }
    }
    __syncthreads();

    // stage 4: dx = g3 @ W3^T ; g2  (wA; prefetch WT2 -> wB)
    ldw64(g_WT + 2*D*D + coff, wB);
    fmaw(sA, wA, base, zp);
    #pragma unroll
    for (int m = 0; m < 4; m++) szp[0][h][m][j] = zp[m];
    __syncthreads();
    #pragma unroll
    for (int m = 0; m < 4; m++){
        z[m] = szp[0][0][m][j] + szp[0][1][m][j];
        if (h == 0){
            float gg = z[m]*dsiluf(z3[m]);
            sB[m][j] = gg; g_G[2*N*D + (t0+m)*D + j] = gg;
        }
    }
    __syncthreads();

    // stage 5: dx = g2 @ W2^T ; g1  (wB; prefetch WT1 -> wA)
    ldw64(g_WT + 1*D*D + coff, wA);
    fmaw(sB, wB, base, zp);
    #pragma unroll
    for (int m = 0; m < 4; m++) szp[0][h][m][j] = zp[m];
    __syncthreads();
    #pragma unroll
    for (int m = 0; m < 4; m++){
        z[m] = szp[0][0][m][j] + szp[0][1][m][j];
        if (h == 0){
            float gg = z[m]*dsiluf(z2[m]);
            sA[m][j] = gg; g_G[1*N*D + (t0+m)*D + j] = gg;
        }
    }
    __syncthreads();

    // stage 6: dx = g1 @ W1^T ; g0  (wA)
    fmaw(sA, wA, base, zp);
    #pragma unroll
    for (int m = 0; m < 4; m++) szp[0][h][m][j] = zp[m];
    __syncthreads();
    if (h == 0){
        #pragma unroll
        for (int m = 0; m < 4; m++){
            float zz = szp[0][0][m][j] + szp[0][1][m][j];
            g_G[0*N*D + (t0+m)*D + j] = zz*dsiluf(z1[m]);
        }
    }
}

// ---------------- scan-coefficient matrix (parallel over s) ----------------
__global__ void chat_kernel(){
    __shared__ float sam[N], sdk[N];
    int s = blockIdx.x*128 + threadIdx.x;
    for (int i = threadIdx.x; i < N; i += 128){ sam[i] = g_am[i]; sdk[i] = g_dk[i]; }
    __syncthreads();
    float m = 0.f, c = 0.f;
    float nl = -g_lr[s];
    for (int t = 0; t < N; t++){
        float out;
        if (t < s) out = 0.f;
        else if (t == s){ m = 1.f; c = 1.f; out = nl; }
        else {
            m *= sam[t];
            c = sdk[t]*c + m;
            out = nl*c;
        }
        g_Chat[t*N + s] = out;
    }
}

// ---------------- fused attention layer ----------------
__global__ __launch_bounds__(256) void layer_kernel(const float* __restrict__ Wmem,
                                                    int layer, int first){
    extern __shared__ float sm[];
    float* Xs = sm;                 // [TT][STR]
    float* As = Xs + TT*STR;        // [SC][STR]
    float* Gs = As + SC*STR;        // [WC][STR]
    float* Cs = Gs + WC*STR;        // [TT][CSTR]
    float* Ps = Cs + TT*CSTR;       // [TT][PSTR]

    int id = blockIdx.x;
    int a, b; bool isW;
    if (id < NREAL){
        int r = id; a = 0;
        while (r >= 2*a + 2){ r -= 2*a + 2; a++; }
        b = r; isW = false;
    } else {
        int q = id - NREAL; a = q >> 2; b = q & 3; isW = true;
    }
    int t0 = a*TT;
    int tid = threadIdx.x;

    const float* Xsrc = first ? g_q : g_X;
    for (int e = tid; e < TT*32; e += 256){
        int t = e >> 5, k4 = (e & 31)*4;
        *reinterpret_cast<float4*>(&Xs[t*STR + k4]) =
            *reinterpret_cast<const float4*>(&Xsrc[(t0+t)*D + k4]);
    }
    if (!isW){
        const float* Al = g_A + layer*N*D;
        const float* Gl = g_G + layer*N*D;
        int s0 = b*SC;
        for (int e = tid; e < SC*32; e += 256){
            int r = e >> 5, k4 = (e & 31)*4;
            *reinterpret_cast<float4*>(&As[r*STR + k4]) =
                *reinterpret_cast<const float4*>(&Al[(s0+r)*D + k4]);
        }
        for (int e = tid; e < SC*32; e += 256){
            int r = e >> 5, k4 = (e & 31)*4;
            *reinterpret_cast<float4*>(&Gs[r*STR + k4]) =
                *reinterpret_cast<const float4*>(&Gl[(s0+r)*D + k4]);
        }
        for (int e = tid; e < TT*4; e += 256){
            int t = e >> 2, s4 = (e & 3)*4;
            *reinterpret_cast<float4*>(&Cs[t*CSTR + s4]) =
                *reinterpret_cast<const float4*>(&g_Chat[(t0+t)*N + s0 + s4]);
        }
    } else {
        const float* Wl = Wmem + layer*D*D;
        int w0 = b*WC;
        for (int e = tid; e < WC*32; e += 256){
            int r = e >> 5, k4 = (e & 31)*4;
            *reinterpret_cast<float4*>(&Gs[r*STR + k4]) =
                *reinterpret_cast<const float4*>(&Wl[(w0+r)*D + k4]);
        }
    }
    __syncthreads();

    // ---- phase 1 (real): S = (X @ A^T) ⊙ Chat -> Ps ----
    if (!isW){
        int sx16 = tid & 15;
        int tg   = tid >> 4;
        float c0 = 0.f, c1 = 0.f;
        const float* ar  = As + sx16*STR;
        const float* x0r = Xs + (tg*2+0)*STR;
        const float* x1r = Xs + (tg*2+1)*STR;
        #pragma unroll 8
        for (int k = 0; k < D; k += 4){
            float4 av = *reinterpret_cast<const float4*>(&ar[k]);
            float4 x0 = *reinterpret_cast<const float4*>(&x0r[k]);
            float4 x1 = *reinterpret_cast<const float4*>(&x1r[k]);
            c0 += x0.x*av.x + x0.y*av.y + x0.z*av.z + x0.w*av.w;
            c1 += x1.x*av.x + x1.y*av.y + x1.z*av.z + x1.w*av.w;
        }
        Ps[(tg*2+0)*PSTR + sx16] = c0 * Cs[(tg*2+0)*CSTR + sx16];
        Ps[(tg*2+1)*PSTR + sx16] = c1 * Cs[(tg*2+1)*CSTR + sx16];
    }
    __syncthreads();

    // ---- phase 2: Y_slice = P @ G ----
    int tx = tid & 31, ty = tid >> 5;
    const float* Psrc = isW ? (Xs + b*WC) : Ps;
    int pst = isW ? STR : PSTR;
    int sc  = isW ? WC : SC;

    float y[4][4];
    #pragma unroll
    for (int i = 0; i < 4; i++)
        #pragma unroll
        for (int jj = 0; jj < 4; jj++) y[i][jj] = 0.f;

    #pragma unroll 4
    for (int s = 0; s < sc; s += 4){
        float4 g0 = *reinterpret_cast<const float4*>(&Gs[(s+0)*STR + tx*4]);
        float4 g1 = *reinterpret_cast<const float4*>(&Gs[(s+1)*STR + tx*4]);
        float4 g2 = *reinterpret_cast<const float4*>(&Gs[(s+2)*STR + tx*4]);
        float4 g3 = *reinterpret_cast<const float4*>(&Gs[(s+3)*STR + tx*4]);
        #pragma unroll
        for (int i = 0; i < 4; i++){
            float4 p = *reinterpret_cast<const float4*>(&Psrc[(ty*4+i)*pst + s]);
            y[i][0] += p.x*g0.x + p.y*g1.x + p.z*g2.x + p.w*g3.x;
            y[i][1] += p.x*g0.y + p.y*g1.y + p.z*g2.y + p.w*g3.y;
            y[i][2] += p.x*g0.z + p.y*g1.z + p.z*g2.z + p.w*g3.z;
            y[i][3] += p.x*g0.w + p.y*g1.w + p.z*g2.w + p.w*g3.w;
        }
    }
    int slice = isW ? (32 + b) : b;
    #pragma unroll
    for (int i = 0; i < 4; i++){
        float4 v; v.x=y[i][0]; v.y=y[i][1]; v.z=y[i][2]; v.w=y[i][3];
        *reinterpret_cast<float4*>(&g_Yp[((slice*N) + t0 + ty*4 + i)*D + tx*4]) = v;
    }
}

// ---------------- reduce: slice-parallel, one block per token ----------------
__global__ __launch_bounds__(128) void reduce_kernel(float* __restrict__ out, int last){
    int t = blockIdx.x;
    int tid = threadIdx.x;
    int tx = tid & 31, sg = tid >> 5;
    const float4* Yp = reinterpret_cast<const float4*>(g_Yp);
    int idx = t*32 + tx;

    float4 acc = Yp[(32 + sg)*(N*32) + idx];

    int nr = (t >> 4) + 1;
    #pragma unroll 4
    for (int c = sg; c < nr; c += 4){
        float4 p = Yp[c*(N*32) + idx];
        acc.x += p.x; acc.y += p.y; acc.z += p.z; acc.w += p.w;
    }

    __shared__ float4 sred[128];
    sred[tid] = acc;
    __syncthreads();
    if (sg == 0){
        float4 a = sred[tx], b = sred[32+tx], c2 = sred[64+tx], d = sred[96+tx];
        float ax = a.x+b.x+c2.x+d.x;
        float ay = a.y+b.y+c2.y+d.y;
        float az = a.z+b.z+c2.z+d.z;
        float aw = a.w+b.w+c2.w+d.w;
        float4 r;
        if (last){ r.x = ax; r.y = ay; r.z = az; r.w = aw; }
        else     { r.x = siluf(ax); r.y = siluf(ay); r.z = siluf(az); r.w = siluf(aw); }
        float4* dst = last ? reinterpret_cast<float4*>(out) : reinterpret_cast<float4*>(g_X);
        dst[idx] = r;
    }
}

// ---------------- launch ----------------
extern "C" void kernel_launch(void* const* d_in, const int* in_sizes, int n_in,
                              void* d_out, int out_size){
    const float* seq    = (const float*)d_in[0];
    const float* Wmem   = (const float*)d_in[1];
    const float* Wq     = (const float*)d_in[2];
    const float* Wkv    = (const float*)d_in[3];
    const float* Wmom   = (const float*)d_in[4];
    const float* Wstep  = (const float*)d_in[5];
    const float* Wdecay = (const float*)d_in[6];
    float* out = (float*)d_out;

    size_t smem = (size_t)(TT*STR + SC*STR + WC*STR + TT*CSTR + TT*PSTR)*sizeof(float); // 47360
    cudaFuncSetAttribute(layer_kernel, cudaFuncAttributeMaxDynamicSharedMemorySize, (int)smem);

    tr_kernel<<<DEPTH, 128>>>(Wmem);
    token_kernel<<<N/4, 256>>>(seq, Wmem, Wq, Wkv, Wmom, Wstep, Wdecay);
    chat_kernel<<<4, 128>>>();

    layer_kernel<<<NBLK, 256, smem>>>(Wmem, 0, 1);
    reduce_kernel<<<N, 128>>>(out, 0);
    layer_kernel<<<NBLK, 256, smem>>>(Wmem, 1, 0);
    reduce_kernel<<<N, 128>>>(out, 0);
    layer_kernel<<<NBLK, 256, smem>>>(Wmem, 2, 0);
    reduce_kernel<<<N, 128>>>(out, 0);
    layer_kernel<<<NBLK, 256, smem>>>(Wmem, 3, 0);
    reduce_kernel<<<N, 128>>>(out, 1);
}